// round 1
// baseline (speedup 1.0000x reference)
#include <cuda_runtime.h>
#include <cstdint>

#define NN   51200
#define NE   819200
#define NG   256
#define NN2  102400
#define NA   204800
#define NE2  409600
#define ND   64
#define NL   5
#define NNI2 36
#define NNAF 40
#define FEPS 1e-5f

// ---------------- device scratch (static, no allocation) ----------------
__device__ float g_h[NN * ND];
__device__ float g_agg[NN * ND];
__device__ float g_h2[NN * ND];

__device__ int g_deg1[NN];
__device__ int g_rowptr1[NN + 1];
__device__ int g_cursor1[NN];
__device__ int g_adj1[NE + NN];
__device__ int g_cnt1[NN * 6];
__device__ int g_cnt2[NN * 3];

__device__ int g_deg2[NN2];
__device__ int g_rowptr2[NN2 + 1];
__device__ int g_cursor2[NN2];
__device__ int g_adj2[NE2];

__device__ float g_xpf[NN2 * ND];
__device__ int   g_iso[NN2];
__device__ float g_zr[NN2 * ND];
__device__ float g_zroot[NN2 * ND];

__device__ float g_bnsum[ND];
__device__ float g_bnsq[ND];
__device__ float g_scale[ND];
__device__ float g_shift[ND];

__device__ float g_x1[NG * ND];
__device__ float g_x2[NG * ND];

// ---------------- graph-state zero ----------------
__global__ void k_zero_state() {
    int i = blockIdx.x * blockDim.x + threadIdx.x;
    int stride = gridDim.x * blockDim.x;
    for (int j = i; j < NN; j += stride) g_deg1[j] = 0;
    for (int j = i; j < 6 * NN; j += stride) g_cnt1[j] = 0;
    for (int j = i; j < 3 * NN; j += stride) g_cnt2[j] = 0;
    for (int j = i; j < NN2; j += stride) g_deg2[j] = 0;
}

// ---------------- degree / attr-count ----------------
__global__ void k_count1(const int* __restrict__ ei, const int* __restrict__ ea) {
    int e = blockIdx.x * blockDim.x + threadIdx.x;
    if (e >= NE) return;
    int dst = ei[NE + e];
    atomicAdd(&g_deg1[dst], 1);
    atomicAdd(&g_cnt1[dst * 6 + ea[2 * e]], 1);
    atomicAdd(&g_cnt2[dst * 3 + ea[2 * e + 1]], 1);
}

__global__ void k_self() {  // self loops: attr (4,0)
    int n = blockIdx.x * blockDim.x + threadIdx.x;
    if (n >= NN) return;
    g_deg1[n] += 1;
    g_cnt1[n * 6 + 4] += 1;
    g_cnt2[n * 3 + 0] += 1;
}

__global__ void k_count2(const int* __restrict__ ei2) {
    int e = blockIdx.x * blockDim.x + threadIdx.x;
    if (e >= NE2) return;
    atomicAdd(&g_deg2[ei2[NE2 + e]], 1);
}

// ---------------- single-block exclusive scan ----------------
__global__ void k_scan(int which) {
    const int* cnt = which ? g_deg2 : g_deg1;
    int* rowptr = which ? g_rowptr2 : g_rowptr1;
    int* cursor = which ? g_cursor2 : g_cursor1;
    int n = which ? NN2 : NN;

    __shared__ int warp_sums[32];
    __shared__ int carry_s;
    int tid = threadIdx.x, lane = tid & 31, wid = tid >> 5;
    if (tid == 0) carry_s = 0;
    __syncthreads();

    for (int base = 0; base < n; base += 1024) {
        int i = base + tid;
        int v = (i < n) ? cnt[i] : 0;
        int inc = v;
        #pragma unroll
        for (int o = 1; o < 32; o <<= 1) {
            int t = __shfl_up_sync(0xffffffffu, inc, o);
            if (lane >= o) inc += t;
        }
        if (lane == 31) warp_sums[wid] = inc;
        __syncthreads();
        if (wid == 0) {
            int s = warp_sums[lane];
            int si = s;
            #pragma unroll
            for (int o = 1; o < 32; o <<= 1) {
                int t = __shfl_up_sync(0xffffffffu, si, o);
                if (lane >= o) si += t;
            }
            warp_sums[lane] = si - s;  // exclusive warp offsets
        }
        __syncthreads();
        int excl = carry_s + warp_sums[wid] + inc - v;
        if (i < n) { rowptr[i] = excl; cursor[i] = excl; }
        __syncthreads();
        if (tid == 1023) carry_s += warp_sums[31] + inc;  // tile total
        __syncthreads();
    }
    if (threadIdx.x == 0) rowptr[n] = carry_s;
}

// ---------------- CSR fill ----------------
__global__ void k_fill1(const int* __restrict__ ei) {
    int e = blockIdx.x * blockDim.x + threadIdx.x;
    if (e >= NE) return;
    int dst = ei[NE + e];
    int pos = atomicAdd(&g_cursor1[dst], 1);
    g_adj1[pos] = ei[e];
}
__global__ void k_fillself() {
    int n = blockIdx.x * blockDim.x + threadIdx.x;
    if (n >= NN) return;
    int pos = atomicAdd(&g_cursor1[n], 1);
    g_adj1[pos] = n;
}
__global__ void k_fill2(const int* __restrict__ ei2) {
    int e = blockIdx.x * blockDim.x + threadIdx.x;
    if (e >= NE2) return;
    int dst = ei2[NE2 + e];
    int pos = atomicAdd(&g_cursor2[dst], 1);
    g_adj2[pos] = ei2[e];
}

// ---------------- embed: h = relu(x @ embW + embB) ----------------
__global__ void k_embed(const float* __restrict__ x, const float* __restrict__ W,
                        const float* __restrict__ b) {
    __shared__ float Ws[NNAF * ND];
    __shared__ float bs[ND];
    __shared__ float row[NNAF];
    int tid = threadIdx.x;  // blockDim = 64
    for (int i = tid; i < NNAF * ND; i += 64) Ws[i] = W[i];
    bs[tid] = b[tid];
    __syncthreads();
    for (int r = blockIdx.x; r < NN; r += gridDim.x) {
        if (tid < NNAF) row[tid] = x[(size_t)r * NNAF + tid];
        __syncthreads();
        float acc = bs[tid];
        #pragma unroll
        for (int k = 0; k < NNAF; k++) acc = fmaf(row[k], Ws[k * ND + tid], acc);
        g_h[(size_t)r * ND + tid] = fmaxf(acc, 0.f);
        __syncthreads();
    }
}

// ---------------- GIN aggregation (warp per node) ----------------
__global__ void k_agg1(const float* __restrict__ e1, const float* __restrict__ e2) {
    int warp = (blockIdx.x * blockDim.x + threadIdx.x) >> 5;
    int lane = threadIdx.x & 31;
    if (warp >= NN) return;
    int n = warp;
    float ax = 0.f, ay = 0.f;
    #pragma unroll
    for (int a = 0; a < 6; a++) {
        float c = (float)__ldg(&g_cnt1[n * 6 + a]);
        float2 w = __ldg((const float2*)(e1 + a * ND + 2 * lane));
        ax = fmaf(c, w.x, ax); ay = fmaf(c, w.y, ay);
    }
    #pragma unroll
    for (int a = 0; a < 3; a++) {
        float c = (float)__ldg(&g_cnt2[n * 3 + a]);
        float2 w = __ldg((const float2*)(e2 + a * ND + 2 * lane));
        ax = fmaf(c, w.x, ax); ay = fmaf(c, w.y, ay);
    }
    int beg = __ldg(&g_rowptr1[n]), end = __ldg(&g_rowptr1[n + 1]);
    int j = beg;
    for (; j + 32 <= end; j += 32) {
        int s = __ldg(&g_adj1[j + lane]);
        #pragma unroll
        for (int t = 0; t < 32; t++) {
            int src = __shfl_sync(0xffffffffu, s, t);
            float2 v = __ldg((const float2*)(g_h + ((size_t)src << 6) + (lane << 1)));
            ax += v.x; ay += v.y;
        }
    }
    if (j < end) {
        int idx = j + lane;
        int s = (idx < end) ? __ldg(&g_adj1[idx]) : 0;
        int cnt = end - j;  // warp-uniform
        for (int t = 0; t < cnt; t++) {
            int src = __shfl_sync(0xffffffffu, s, t);
            float2 v = __ldg((const float2*)(g_h + ((size_t)src << 6) + (lane << 1)));
            ax += v.x; ay += v.y;
        }
    }
    float2 o; o.x = ax; o.y = ay;
    *(float2*)(g_agg + ((size_t)n << 6) + (lane << 1)) = o;
}

// ---------------- GIN MLP (64->128 relu ->64) + BN partial sums ----------------
__global__ void k_bnzero() {
    int t = threadIdx.x;
    if (t < ND) { g_bnsum[t] = 0.f; g_bnsq[t] = 0.f; }
}

__global__ __launch_bounds__(128) void k_mlp(const float* __restrict__ W1,
                                             const float* __restrict__ b1,
                                             const float* __restrict__ W2,
                                             const float* __restrict__ b2) {
    __shared__ float4 rows4[16];   // 64 floats
    __shared__ float4 mid4[32];    // 128 floats
    __shared__ float part[128];
    __shared__ float b1s[128];
    __shared__ float b2s[64];
    int tid = threadIdx.x;

    // register-resident weight columns
    float w1c[64];
    #pragma unroll
    for (int k = 0; k < 64; k++) w1c[k] = __ldg(&W1[k * 128 + tid]);
    int c2 = tid & 63, hh = tid >> 6;
    float w2c[64];
    #pragma unroll
    for (int k = 0; k < 64; k++) w2c[k] = __ldg(&W2[(hh * 64 + k) * 64 + c2]);

    b1s[tid] = b1[tid];
    if (tid < 64) b2s[tid] = b2[tid];

    float lsum = 0.f, lsq = 0.f;
    float* rowf = (float*)rows4;
    float* midf = (float*)mid4;
    __syncthreads();

    for (int r = blockIdx.x; r < NN; r += gridDim.x) {
        if (tid < 64) rowf[tid] = g_agg[(size_t)r * 64 + tid];
        __syncthreads();
        // stage 1
        float a0 = 0.f, a1 = 0.f;
        #pragma unroll
        for (int kk = 0; kk < 16; kk++) {
            float4 rv = rows4[kk];
            a0 = fmaf(rv.x, w1c[4 * kk + 0], a0);
            a1 = fmaf(rv.y, w1c[4 * kk + 1], a1);
            a0 = fmaf(rv.z, w1c[4 * kk + 2], a0);
            a1 = fmaf(rv.w, w1c[4 * kk + 3], a1);
        }
        midf[tid] = fmaxf(a0 + a1 + b1s[tid], 0.f);
        __syncthreads();
        // stage 2 (split K in halves across thread groups)
        float s0 = 0.f, s1 = 0.f;
        #pragma unroll
        for (int kk = 0; kk < 16; kk++) {
            float4 mv = mid4[hh * 16 + kk];
            s0 = fmaf(mv.x, w2c[4 * kk + 0], s0);
            s1 = fmaf(mv.y, w2c[4 * kk + 1], s1);
            s0 = fmaf(mv.z, w2c[4 * kk + 2], s0);
            s1 = fmaf(mv.w, w2c[4 * kk + 3], s1);
        }
        part[tid] = s0 + s1;
        __syncthreads();
        if (tid < 64) {
            float o = part[tid] + part[tid + 64] + b2s[tid];
            g_h2[(size_t)r * 64 + tid] = o;
            lsum += o; lsq += o * o;
        }
        __syncthreads();
    }
    if (tid < 64) {
        atomicAdd(&g_bnsum[tid], lsum);
        atomicAdd(&g_bnsq[tid], lsq);
    }
}

__global__ void k_bnfin(const float* __restrict__ gamma, const float* __restrict__ beta) {
    int t = threadIdx.x;
    if (t < ND) {
        float mu = g_bnsum[t] * (1.f / (float)NN);
        float var = g_bnsq[t] * (1.f / (float)NN) - mu * mu;
        float sc = gamma[t] * rsqrtf(var + FEPS);
        g_scale[t] = sc;
        g_shift[t] = beta[t] - mu * sc;
    }
}

__global__ void k_norm(int relu) {
    int idx = blockIdx.x * blockDim.x + threadIdx.x;
    if (idx >= NN * 16) return;
    float4 v = *(const float4*)(g_h2 + (size_t)idx * 4);
    int c = (idx & 15) * 4;
    float4 o;
    o.x = g_scale[c + 0] * v.x + g_shift[c + 0];
    o.y = g_scale[c + 1] * v.y + g_shift[c + 1];
    o.z = g_scale[c + 2] * v.z + g_shift[c + 2];
    o.w = g_scale[c + 3] * v.w + g_shift[c + 3];
    if (relu) {
        o.x = fmaxf(o.x, 0.f); o.y = fmaxf(o.y, 0.f);
        o.z = fmaxf(o.z, 0.f); o.w = fmaxf(o.w, 0.f);
    }
    *(float4*)(g_h + (size_t)idx * 4) = o;
}

// ---------------- pools (contiguous segments) ----------------
__global__ void k_pool(int which) {
    int b = blockIdx.x, t = threadIdx.x;
    if (which == 0) {
        const float* p = g_h + (size_t)b * 200 * 64 + t;
        float s = 0.f;
        for (int r = 0; r < 200; r++) s += p[(size_t)r * 64];
        g_x1[b * 64 + t] = s * (1.f / 200.f);
    } else {
        const float* p = g_xpf + (size_t)b * 400 * 64 + t;
        float s = 0.f;
        for (int r = 0; r < 400; r++) s += p[(size_t)r * 64];
        g_x2[b * 64 + t] = s * (1.f / 400.f);
    }
}

// ---------------- 2-set branch ----------------
__global__ void k_iso(const float* __restrict__ isoT) {
    int i = blockIdx.x * blockDim.x + threadIdx.x;
    if (i >= NN2) return;
    const float* row = isoT + (size_t)i * NNI2;
    int r = 0;
    for (int k = 0; k < NNI2; k++)
        if (row[k] > 0.5f) r = k;
    g_iso[i] = r;
}

__global__ void k_xp(const int* __restrict__ asg0) {
    int idx = blockIdx.x * blockDim.x + threadIdx.x;
    if (idx >= NN2 * ND) return;
    int i = idx >> 6, d = idx & 63;
    int a = __ldg(&asg0[2 * i]);
    int b = __ldg(&asg0[2 * i + 1]);
    g_xpf[idx] = 0.5f * (__ldg(&g_h[(size_t)a * 64 + d]) + __ldg(&g_h[(size_t)b * 64 + d]));
}

// project: zr = xpf@Wrel[0:64] (+Wrel[64+iso]); zroot = xpf@Wroot[0:64] (+Wroot[64+iso])
__global__ __launch_bounds__(128) void k_proj(const float* __restrict__ Wrel,
                                              const float* __restrict__ Wroot,
                                              int use_iso) {
    __shared__ float4 rows4[16];
    int tid = threadIdx.x;
    int c = tid & 63, msel = tid >> 6;  // 0 -> rel, 1 -> root
    const float* Wm = msel ? Wroot : Wrel;
    float wc[64];
    #pragma unroll
    for (int k = 0; k < 64; k++) wc[k] = __ldg(&Wm[k * 64 + c]);
    float* rowf = (float*)rows4;
    float* outp = msel ? g_zroot : g_zr;
    __syncthreads();

    for (int r = blockIdx.x; r < NN2; r += gridDim.x) {
        if (tid < 64) rowf[tid] = g_xpf[(size_t)r * 64 + tid];
        __syncthreads();
        float acc = 0.f;
        if (use_iso) {
            int is = __ldg(&g_iso[r]);
            acc = __ldg(&Wm[(64 + is) * 64 + c]);
        }
        float a0 = 0.f, a1 = 0.f;
        #pragma unroll
        for (int kk = 0; kk < 16; kk++) {
            float4 rv = rows4[kk];
            a0 = fmaf(rv.x, wc[4 * kk + 0], a0);
            a1 = fmaf(rv.y, wc[4 * kk + 1], a1);
            a0 = fmaf(rv.z, wc[4 * kk + 2], a0);
            a1 = fmaf(rv.w, wc[4 * kk + 3], a1);
        }
        outp[(size_t)r * 64 + c] = acc + a0 + a1;
        __syncthreads();
    }
}

// conv aggregate: out[i] = relu( sum_{src in CSR2[i]} zr[src] + brel + zroot[i] )
__global__ void k_cagg(const float* __restrict__ brel) {
    int warp = (blockIdx.x * blockDim.x + threadIdx.x) >> 5;
    int lane = threadIdx.x & 31;
    if (warp >= NN2) return;
    int n = warp;
    float2 z = __ldg((const float2*)(g_zroot + ((size_t)n << 6) + (lane << 1)));
    float ax = z.x + __ldg(&brel[2 * lane]);
    float ay = z.y + __ldg(&brel[2 * lane + 1]);
    int beg = __ldg(&g_rowptr2[n]), end = __ldg(&g_rowptr2[n + 1]);
    int j = beg;
    for (; j + 32 <= end; j += 32) {
        int s = __ldg(&g_adj2[j + lane]);
        #pragma unroll
        for (int t = 0; t < 32; t++) {
            int src = __shfl_sync(0xffffffffu, s, t);
            float2 v = __ldg((const float2*)(g_zr + ((size_t)src << 6) + (lane << 1)));
            ax += v.x; ay += v.y;
        }
    }
    if (j < end) {
        int idx = j + lane;
        int s = (idx < end) ? __ldg(&g_adj2[idx]) : 0;
        int cnt = end - j;
        for (int t = 0; t < cnt; t++) {
            int src = __shfl_sync(0xffffffffu, s, t);
            float2 v = __ldg((const float2*)(g_zr + ((size_t)src << 6) + (lane << 1)));
            ax += v.x; ay += v.y;
        }
    }
    float2 o; o.x = fmaxf(ax, 0.f); o.y = fmaxf(ay, 0.f);
    *(float2*)(g_xpf + ((size_t)n << 6) + (lane << 1)) = o;
}

// ---------------- readout MLP ----------------
__global__ void k_readout(const float* __restrict__ W0, const float* __restrict__ b0,
                          const float* __restrict__ W1, const float* __restrict__ b1,
                          const float* __restrict__ W2, const float* __restrict__ b2,
                          const float* __restrict__ lW, const float* __restrict__ lb,
                          float* __restrict__ out) {
    __shared__ float m[128];
    __shared__ float h0[64];
    __shared__ float h1[32];
    __shared__ float h2s[16];
    int b = blockIdx.x, t = threadIdx.x;  // 64 threads
    m[t] = g_x1[b * 64 + t];
    m[64 + t] = g_x2[b * 64 + t];
    __syncthreads();
    float acc = __ldg(&b0[t]);
    #pragma unroll 4
    for (int k = 0; k < 128; k++) acc = fmaf(m[k], __ldg(&W0[k * 64 + t]), acc);
    h0[t] = fmaxf(acc, 0.f);
    __syncthreads();
    if (t < 32) {
        float a = __ldg(&b1[t]);
        for (int k = 0; k < 64; k++) a = fmaf(h0[k], __ldg(&W1[k * 32 + t]), a);
        h1[t] = fmaxf(a, 0.f);
    }
    __syncthreads();
    if (t < 16) {
        float a = __ldg(&b2[t]);
        for (int k = 0; k < 32; k++) a = fmaf(h1[k], __ldg(&W2[k * 16 + t]), a);
        h2s[t] = fmaxf(a, 0.f);
    }
    __syncthreads();
    if (t == 0) {
        float a = __ldg(&lb[0]);
        for (int k = 0; k < 16; k++) a = fmaf(h2s[k], __ldg(&lW[k]), a);
        out[b] = a;
    }
}

// ---------------- launch ----------------
extern "C" void kernel_launch(void* const* d_in, const int* in_sizes, int n_in,
                              void* d_out, int out_size) {
    (void)in_sizes; (void)n_in; (void)out_size;
    const float* x    = (const float*)d_in[0];
    const int*   ei   = (const int*)d_in[1];
    const int*   ea   = (const int*)d_in[2];
    const float* isoT = (const float*)d_in[4];
    const int*   ei2  = (const int*)d_in[5];
    const int*   asg  = (const int*)d_in[6];
    const float* embW = (const float*)d_in[8];
    const float* embB = (const float*)d_in[9];
    const float* gW1  = (const float*)d_in[10];
    const float* gb1  = (const float*)d_in[11];
    const float* gW2  = (const float*)d_in[12];
    const float* gb2  = (const float*)d_in[13];
    const float* ee1  = (const float*)d_in[14];
    const float* ee2  = (const float*)d_in[15];
    const float* bng  = (const float*)d_in[16];
    const float* bnb  = (const float*)d_in[17];
    const float* i1rW = (const float*)d_in[18];
    const float* i1rb = (const float*)d_in[19];
    const float* i1oW = (const float*)d_in[20];
    const float* i2rW = (const float*)d_in[21];
    const float* i2rb = (const float*)d_in[22];
    const float* i2oW = (const float*)d_in[23];
    const float* rW0  = (const float*)d_in[24];
    const float* rb0  = (const float*)d_in[25];
    const float* rW1  = (const float*)d_in[26];
    const float* rb1  = (const float*)d_in[27];
    const float* rW2  = (const float*)d_in[28];
    const float* rb2  = (const float*)d_in[29];
    const float* lW   = (const float*)d_in[30];
    const float* lb   = (const float*)d_in[31];
    float* out = (float*)d_out;

    // ---- CSR build (per call; edge structure fixed, cost amortized small) ----
    k_zero_state<<<256, 256>>>();
    k_count1<<<NE / 256, 256>>>(ei, ea);
    k_self<<<NN / 256, 256>>>();
    k_count2<<<NE2 / 256, 256>>>(ei2);
    k_scan<<<1, 1024>>>(0);
    k_scan<<<1, 1024>>>(1);
    k_fill1<<<NE / 256, 256>>>(ei);
    k_fillself<<<NN / 256, 256>>>();
    k_fill2<<<NE2 / 256, 256>>>(ei2);

    // ---- node embedding ----
    k_embed<<<1024, 64>>>(x, embW, embB);

    // ---- GIN stack ----
    for (int l = 0; l < NL; l++) {
        k_agg1<<<NN / 8, 256>>>(ee1 + (size_t)l * 6 * ND, ee2 + (size_t)l * 3 * ND);
        k_bnzero<<<1, 64>>>();
        k_mlp<<<2048, 128>>>(gW1 + (size_t)l * ND * 128, gb1 + (size_t)l * 128,
                             gW2 + (size_t)l * 128 * ND, gb2 + (size_t)l * ND);
        k_bnfin<<<1, 64>>>(bng + (size_t)l * ND, bnb + (size_t)l * ND);
        k_norm<<<NN * 16 / 256, 256>>>((l < NL - 1) ? 1 : 0);
    }

    // ---- graph mean pool of node_rep ----
    k_pool<<<NG, 64>>>(0);

    // ---- 2-set branch ----
    k_iso<<<(NN2 + 255) / 256, 256>>>(isoT);
    k_xp<<<NN2 * ND / 256, 256>>>(asg);
    k_proj<<<2048, 128>>>(i1rW, i1oW, 1);
    k_cagg<<<NN2 / 8, 256>>>(i1rb);
    k_proj<<<2048, 128>>>(i2rW, i2oW, 0);
    k_cagg<<<NN2 / 8, 256>>>(i2rb);
    k_pool<<<NG, 64>>>(1);

    // ---- readout ----
    k_readout<<<NG, 64>>>(rW0, rb0, rW1, rb1, rW2, rb2, lW, lb, out);
}

// round 2
// speedup vs baseline: 1.1306x; 1.1306x over previous
#include <cuda_runtime.h>
#include <cstdint>

#define NN   51200
#define NE   819200
#define NG   256
#define NN2  102400
#define NA   204800
#define NE2  409600
#define ND   64
#define NL   5
#define NNI2 36
#define NNAF 40
#define FEPS 1e-5f

typedef unsigned long long u64;

// ---------------- f32x2 packed helpers ----------------
__device__ __forceinline__ u64 pk2(float x, float y) {
    u64 r; asm("mov.b64 %0, {%1,%2};" : "=l"(r) : "f"(x), "f"(y)); return r;
}
__device__ __forceinline__ float2 up2(u64 v) {
    float2 r; asm("mov.b64 {%0,%1}, %2;" : "=f"(r.x), "=f"(r.y) : "l"(v)); return r;
}
// d = (a,a) * b + c   elementwise on packed f32 pairs
__device__ __forceinline__ u64 f2fma(float a, u64 b, u64 c) {
    u64 d;
    asm("{\n\t.reg .b64 ra;\n\tmov.b64 ra, {%1,%1};\n\tfma.rn.f32x2 %0, ra, %2, %3;\n\t}"
        : "=l"(d) : "f"(a), "l"(b), "l"(c));
    return d;
}
__device__ __forceinline__ u64 add2(u64 a, u64 b) {
    u64 d; asm("add.rn.f32x2 %0, %1, %2;" : "=l"(d) : "l"(a), "l"(b)); return d;
}

// ---------------- device scratch ----------------
__device__ float g_h[NN * ND];
__device__ float g_agg[NN * ND];
__device__ float g_h2[NN * ND];

__device__ int g_cnt12[NN * 12];
__device__ int g_deg1[NN];
__device__ int g_base1[NN];
__device__ int g_cursor1[NN];
__device__ int g_adj1[NE];
__device__ int g_total1;

__device__ int g_deg2[NN2];
__device__ int g_base2[NN2];
__device__ int g_cursor2[NN2];
__device__ int g_adj2[NE2];
__device__ int g_total2;

__device__ float g_xpf[NN2 * ND];
__device__ int   g_iso[NN2];
__device__ float g_zr[NN2 * ND];
__device__ float g_zroot[NN2 * ND];

__device__ float g_bnsum[ND];
__device__ float g_bnsq[ND];

__device__ float g_x1[NG * ND];
__device__ float g_x2[NG * ND];

// ---------------- zero ----------------
__global__ void k_zero() {
    int i = blockIdx.x * blockDim.x + threadIdx.x;
    int stride = gridDim.x * blockDim.x;
    for (int j = i; j < NN * 12; j += stride) g_cnt12[j] = 0;
    for (int j = i; j < NN2; j += stride) g_deg2[j] = 0;
    if (i == 0) { g_total1 = 0; g_total2 = 0; }
}

// ---------------- counts ----------------
__global__ void k_count1(const int* __restrict__ ei, const int* __restrict__ ea) {
    int e = blockIdx.x * blockDim.x + threadIdx.x;
    if (e >= NE) return;
    int dst = ei[NE + e];
    int a0 = ea[2 * e], a1 = ea[2 * e + 1];
    atomicAdd(&g_cnt12[dst * 12 + a0 * 3 + a1], 1);
}
__global__ void k_count2(const int* __restrict__ ei2) {
    int e = blockIdx.x * blockDim.x + threadIdx.x;
    if (e >= NE2) return;
    atomicAdd(&g_deg2[ei2[NE2 + e]], 1);
}

// ---------------- reserve CSR ranges (warp-aggregated atomics, no scan) ----------------
__global__ void k_reserve() {
    int i = blockIdx.x * blockDim.x + threadIdx.x;
    int lane = threadIdx.x & 31;
    if (i < NN) {
        int d = 0;
        #pragma unroll
        for (int c = 0; c < 12; c++) d += g_cnt12[i * 12 + c];
        g_deg1[i] = d;
        int incl = d;
        #pragma unroll
        for (int o = 1; o < 32; o <<= 1) {
            int t = __shfl_up_sync(0xffffffffu, incl, o);
            if (lane >= o) incl += t;
        }
        int tot = __shfl_sync(0xffffffffu, incl, 31);
        int base = 0;
        if (lane == 0) base = atomicAdd(&g_total1, tot);
        base = __shfl_sync(0xffffffffu, base, 0);
        int start = base + incl - d;
        g_base1[i] = start; g_cursor1[i] = start;
    } else if (i < NN + NN2) {
        int j = i - NN;
        int d = g_deg2[j];
        int incl = d;
        #pragma unroll
        for (int o = 1; o < 32; o <<= 1) {
            int t = __shfl_up_sync(0xffffffffu, incl, o);
            if (lane >= o) incl += t;
        }
        int tot = __shfl_sync(0xffffffffu, incl, 31);
        int base = 0;
        if (lane == 0) base = atomicAdd(&g_total2, tot);
        base = __shfl_sync(0xffffffffu, base, 0);
        int start = base + incl - d;
        g_base2[j] = start; g_cursor2[j] = start;
    }
}

// ---------------- CSR fill ----------------
__global__ void k_fill1(const int* __restrict__ ei) {
    int e = blockIdx.x * blockDim.x + threadIdx.x;
    if (e >= NE) return;
    int dst = ei[NE + e];
    int pos = atomicAdd(&g_cursor1[dst], 1);
    g_adj1[pos] = ei[e];
}
__global__ void k_fill2(const int* __restrict__ ei2) {
    int e = blockIdx.x * blockDim.x + threadIdx.x;
    if (e >= NE2) return;
    int dst = ei2[NE2 + e];
    int pos = atomicAdd(&g_cursor2[dst], 1);
    g_adj2[pos] = ei2[e];
}

// ---------------- embed: h = relu(x @ embW + embB) ----------------
__global__ __launch_bounds__(128) void k_embed(const float* __restrict__ x,
                                               const float* __restrict__ W,
                                               const float* __restrict__ b) {
    __shared__ float Ws[NNAF * ND];
    __shared__ float bs[ND];
    __shared__ float row[2][NNAF];
    int tid = threadIdx.x;
    for (int i = tid; i < NNAF * ND; i += 128) Ws[i] = W[i];
    if (tid < 64) bs[tid] = b[tid];
    __syncthreads();
    int slot = tid >> 6, c = tid & 63;
    for (int base = blockIdx.x * 2; base < NN; base += gridDim.x * 2) {
        if (tid < 2 * NNAF) row[tid / NNAF][tid % NNAF] = x[(size_t)base * NNAF + tid];
        __syncthreads();
        float acc = bs[c];
        #pragma unroll
        for (int k = 0; k < NNAF; k++) acc = fmaf(row[slot][k], Ws[k * 64 + c], acc);
        g_h[(size_t)(base + slot) * 64 + c] = fmaxf(acc, 0.f);
        __syncthreads();
    }
}

// ---------------- GIN aggregation (warp per node) + bn-stat zero ----------------
__global__ __launch_bounds__(256) void k_agg1(const float* __restrict__ e1,
                                              const float* __restrict__ e2) {
    __shared__ float comb[12][64];   // e1[a0]+e2[a1]
    __shared__ float selfe[64];      // e1[4]+e2[0]
    int tid = threadIdx.x;
    for (int idx = tid; idx < 12 * 64; idx += 256) {
        int cc = idx >> 6, d = idx & 63;
        comb[cc][d] = e1[(cc / 3) * 64 + d] + e2[(cc % 3) * 64 + d];
    }
    if (tid < 64) selfe[tid] = e1[4 * 64 + tid] + e2[0 * 64 + tid];
    if (blockIdx.x == 0 && tid < 64) { g_bnsum[tid] = 0.f; g_bnsq[tid] = 0.f; }
    __syncthreads();

    int warp = (blockIdx.x * 256 + tid) >> 5;
    if (warp >= NN) return;
    int n = warp;
    int lane = tid & 31;

    int cnt = (lane < 12) ? __ldg(&g_cnt12[n * 12 + lane]) : 0;

    // self-loop: h[n] + eemb(4,0)
    float2 hv = __ldg((const float2*)(g_h + ((size_t)n << 6) + (lane << 1)));
    float2 se = ((const float2*)selfe)[lane];
    float ax = hv.x + se.x, ay = hv.y + se.y;

    #pragma unroll
    for (int c = 0; c < 12; c++) {
        float cc = (float)__shfl_sync(0xffffffffu, cnt, c);
        float2 w = ((const float2*)comb[c])[lane];
        ax = fmaf(cc, w.x, ax); ay = fmaf(cc, w.y, ay);
    }

    int beg = __ldg(&g_base1[n]);
    int end = beg + __ldg(&g_deg1[n]);
    int j = beg;
    for (; j + 32 <= end; j += 32) {
        int s = __ldg(&g_adj1[j + lane]);
        #pragma unroll
        for (int t = 0; t < 32; t++) {
            int src = __shfl_sync(0xffffffffu, s, t);
            float2 v = __ldg((const float2*)(g_h + ((size_t)src << 6) + (lane << 1)));
            ax += v.x; ay += v.y;
        }
    }
    if (j < end) {
        int idx = j + lane;
        int s = (idx < end) ? __ldg(&g_adj1[idx]) : 0;
        int c = end - j;
        for (int t = 0; t < c; t++) {
            int src = __shfl_sync(0xffffffffu, s, t);
            float2 v = __ldg((const float2*)(g_h + ((size_t)src << 6) + (lane << 1)));
            ax += v.x; ay += v.y;
        }
    }
    float2 o; o.x = ax; o.y = ay;
    *(float2*)(g_agg + ((size_t)n << 6) + (lane << 1)) = o;
}

// ---------------- GIN MLP (64->128 relu ->64), packed f32x2, BN partials ----------------
__global__ __launch_bounds__(128) void k_mlp(const float* __restrict__ W1,
                                             const float* __restrict__ b1,
                                             const float* __restrict__ W2,
                                             const float* __restrict__ b2) {
    __shared__ __align__(16) float rowf[64];
    __shared__ __align__(16) float midf[128];
    __shared__ u64 part[128];
    int tid = threadIdx.x;

    // stage1: col pair p1 -> cols (2p1, 2p1+1); K half kh
    int p1 = tid & 63, kh = tid >> 6;
    u64 w1p[32];
    #pragma unroll
    for (int kk = 0; kk < 32; kk++) {
        int k = kh * 32 + kk;
        w1p[kk] = pk2(__ldg(&W1[k * 128 + 2 * p1]), __ldg(&W1[k * 128 + 2 * p1 + 1]));
    }
    u64 bias1 = (kh == 0) ? pk2(__ldg(&b1[2 * p1]), __ldg(&b1[2 * p1 + 1])) : 0ull;

    // stage2: col pair p2 -> cols (2p2, 2p2+1); K quarter kq
    int p2 = tid & 31, kq = tid >> 5;
    u64 w2p[32];
    #pragma unroll
    for (int kk = 0; kk < 32; kk++) {
        int k = kq * 32 + kk;
        w2p[kk] = pk2(__ldg(&W2[k * 64 + 2 * p2]), __ldg(&W2[k * 64 + 2 * p2 + 1]));
    }
    u64 bias2 = (kq == 0) ? pk2(__ldg(&b2[2 * p2]), __ldg(&b2[2 * p2 + 1])) : 0ull;

    float2 lsum = make_float2(0.f, 0.f), lsq = make_float2(0.f, 0.f);

    for (int r = blockIdx.x; r < NN; r += gridDim.x) {
        if (tid < 64) rowf[tid] = g_agg[(size_t)r * 64 + tid];
        __syncthreads();
        // stage 1
        u64 acc = bias1;
        const float4* rb = (const float4*)(rowf + kh * 32);
        #pragma unroll
        for (int q = 0; q < 8; q++) {
            float4 rv = rb[q];
            acc = f2fma(rv.x, w1p[4 * q + 0], acc);
            acc = f2fma(rv.y, w1p[4 * q + 1], acc);
            acc = f2fma(rv.z, w1p[4 * q + 2], acc);
            acc = f2fma(rv.w, w1p[4 * q + 3], acc);
        }
        part[tid] = acc;
        __syncthreads();
        if (tid < 64) {
            float2 v = up2(add2(part[tid], part[tid + 64]));
            midf[2 * tid] = fmaxf(v.x, 0.f);
            midf[2 * tid + 1] = fmaxf(v.y, 0.f);
        }
        __syncthreads();
        // stage 2
        u64 acc2 = bias2;
        const float4* mb = (const float4*)(midf + kq * 32);
        #pragma unroll
        for (int q = 0; q < 8; q++) {
            float4 mv = mb[q];
            acc2 = f2fma(mv.x, w2p[4 * q + 0], acc2);
            acc2 = f2fma(mv.y, w2p[4 * q + 1], acc2);
            acc2 = f2fma(mv.z, w2p[4 * q + 2], acc2);
            acc2 = f2fma(mv.w, w2p[4 * q + 3], acc2);
        }
        part[tid] = acc2;
        __syncthreads();
        if (tid < 32) {
            float2 v = up2(add2(add2(part[tid], part[tid + 32]),
                                add2(part[tid + 64], part[tid + 96])));
            *(float2*)(g_h2 + (size_t)r * 64 + 2 * tid) = v;
            lsum.x += v.x; lsum.y += v.y;
            lsq.x += v.x * v.x; lsq.y += v.y * v.y;
        }
        __syncthreads();
    }
    if (tid < 32) {
        atomicAdd(&g_bnsum[2 * tid], lsum.x);
        atomicAdd(&g_bnsum[2 * tid + 1], lsum.y);
        atomicAdd(&g_bnsq[2 * tid], lsq.x);
        atomicAdd(&g_bnsq[2 * tid + 1], lsq.y);
    }
}

// ---------------- BN normalize (+relu), scale/shift computed per block ----------------
__global__ void k_norm(const float* __restrict__ gamma, const float* __restrict__ beta,
                       int relu) {
    __shared__ float sc[64], sh[64];
    int tid = threadIdx.x;
    if (tid < 64) {
        float mu = g_bnsum[tid] * (1.f / (float)NN);
        float var = g_bnsq[tid] * (1.f / (float)NN) - mu * mu;
        float s = gamma[tid] * rsqrtf(var + FEPS);
        sc[tid] = s;
        sh[tid] = beta[tid] - mu * s;
    }
    __syncthreads();
    int idx = blockIdx.x * blockDim.x + tid;
    if (idx >= NN * 16) return;
    float4 v = *(const float4*)(g_h2 + (size_t)idx * 4);
    int c = (idx & 15) * 4;
    float4 o;
    o.x = sc[c + 0] * v.x + sh[c + 0];
    o.y = sc[c + 1] * v.y + sh[c + 1];
    o.z = sc[c + 2] * v.z + sh[c + 2];
    o.w = sc[c + 3] * v.w + sh[c + 3];
    if (relu) {
        o.x = fmaxf(o.x, 0.f); o.y = fmaxf(o.y, 0.f);
        o.z = fmaxf(o.z, 0.f); o.w = fmaxf(o.w, 0.f);
    }
    *(float4*)(g_h + (size_t)idx * 4) = o;
}

// ---------------- pools (contiguous segments) ----------------
__global__ void k_pool(int which) {
    int b = blockIdx.x, t = threadIdx.x;
    if (which == 0) {
        const float* p = g_h + (size_t)b * 200 * 64 + t;
        float s = 0.f;
        for (int r = 0; r < 200; r++) s += p[(size_t)r * 64];
        g_x1[b * 64 + t] = s * (1.f / 200.f);
    } else {
        const float* p = g_xpf + (size_t)b * 400 * 64 + t;
        float s = 0.f;
        for (int r = 0; r < 400; r++) s += p[(size_t)r * 64];
        g_x2[b * 64 + t] = s * (1.f / 400.f);
    }
}

// ---------------- 2-set branch ----------------
__global__ void k_iso(const float* __restrict__ isoT) {
    int i = blockIdx.x * blockDim.x + threadIdx.x;
    if (i >= NN2) return;
    const float4* row = (const float4*)(isoT + (size_t)i * NNI2);
    int r = 0;
    #pragma unroll
    for (int q = 0; q < 9; q++) {
        float4 v = __ldg(&row[q]);
        if (v.x > 0.5f) r = 4 * q;
        if (v.y > 0.5f) r = 4 * q + 1;
        if (v.z > 0.5f) r = 4 * q + 2;
        if (v.w > 0.5f) r = 4 * q + 3;
    }
    g_iso[i] = r;
}

__global__ void k_xp(const int* __restrict__ asg0) {
    int idx = blockIdx.x * blockDim.x + threadIdx.x;
    if (idx >= NN2 * ND) return;
    int i = idx >> 6, d = idx & 63;
    int a = __ldg(&asg0[2 * i]);
    int b = __ldg(&asg0[2 * i + 1]);
    g_xpf[idx] = 0.5f * (__ldg(&g_h[(size_t)a * 64 + d]) + __ldg(&g_h[(size_t)b * 64 + d]));
}

// project: zr = xpf@Wrel + iso-row(Wrel); zroot = xpf@Wroot + iso-row(Wroot)
__global__ __launch_bounds__(128) void k_proj(const float* __restrict__ Wrel,
                                              const float* __restrict__ Wroot,
                                              int use_iso) {
    __shared__ __align__(16) float rowf[64];
    __shared__ u64 part[128];
    __shared__ float isoWs[2 * NNI2 * 64];  // only filled if use_iso
    int tid = threadIdx.x;
    int msel = tid >> 6;            // 0 rel, 1 root
    int u = tid & 63;
    int pp = u & 31, kh = u >> 5;   // col pair pp -> cols 2pp,2pp+1; K half kh
    const float* Wm = msel ? Wroot : Wrel;

    u64 wp[32];
    #pragma unroll
    for (int kk = 0; kk < 32; kk++) {
        int k = kh * 32 + kk;
        wp[kk] = pk2(__ldg(&Wm[k * 64 + 2 * pp]), __ldg(&Wm[k * 64 + 2 * pp + 1]));
    }
    if (use_iso) {
        for (int idx = tid; idx < 2 * NNI2 * 64; idx += 128) {
            int m = idx / (NNI2 * 64);
            int rest = idx - m * (NNI2 * 64);
            const float* Wx = m ? Wroot : Wrel;
            isoWs[idx] = Wx[(64 + rest / 64) * 64 + (rest & 63)];
        }
    }
    __syncthreads();

    for (int r = blockIdx.x; r < NN2; r += gridDim.x) {
        if (tid < 64) rowf[tid] = g_xpf[(size_t)r * 64 + tid];
        __syncthreads();
        u64 acc = 0ull;
        const float4* rb = (const float4*)(rowf + kh * 32);
        #pragma unroll
        for (int q = 0; q < 8; q++) {
            float4 rv = rb[q];
            acc = f2fma(rv.x, wp[4 * q + 0], acc);
            acc = f2fma(rv.y, wp[4 * q + 1], acc);
            acc = f2fma(rv.z, wp[4 * q + 2], acc);
            acc = f2fma(rv.w, wp[4 * q + 3], acc);
        }
        part[tid] = acc;
        __syncthreads();
        if (tid < 64) {
            int m = tid >> 5, p = tid & 31;
            float2 v = up2(add2(part[m * 64 + p], part[m * 64 + 32 + p]));
            if (use_iso) {
                int is = __ldg(&g_iso[r]);
                v.x += isoWs[m * (NNI2 * 64) + is * 64 + 2 * p];
                v.y += isoWs[m * (NNI2 * 64) + is * 64 + 2 * p + 1];
            }
            float* outp = m ? g_zroot : g_zr;
            *(float2*)(outp + (size_t)r * 64 + 2 * p) = v;
        }
        __syncthreads();
    }
}

// conv aggregate: xpf[i] = relu( sum_{src} zr[src] + brel + zroot[i] )
__global__ __launch_bounds__(256) void k_cagg(const float* __restrict__ brel) {
    int warp = (blockIdx.x * blockDim.x + threadIdx.x) >> 5;
    int lane = threadIdx.x & 31;
    if (warp >= NN2) return;
    int n = warp;
    float2 z = __ldg((const float2*)(g_zroot + ((size_t)n << 6) + (lane << 1)));
    float ax = z.x + __ldg(&brel[2 * lane]);
    float ay = z.y + __ldg(&brel[2 * lane + 1]);
    int beg = __ldg(&g_base2[n]);
    int end = beg + __ldg(&g_deg2[n]);
    int j = beg;
    for (; j + 32 <= end; j += 32) {
        int s = __ldg(&g_adj2[j + lane]);
        #pragma unroll
        for (int t = 0; t < 32; t++) {
            int src = __shfl_sync(0xffffffffu, s, t);
            float2 v = __ldg((const float2*)(g_zr + ((size_t)src << 6) + (lane << 1)));
            ax += v.x; ay += v.y;
        }
    }
    if (j < end) {
        int idx = j + lane;
        int s = (idx < end) ? __ldg(&g_adj2[idx]) : 0;
        int c = end - j;
        for (int t = 0; t < c; t++) {
            int src = __shfl_sync(0xffffffffu, s, t);
            float2 v = __ldg((const float2*)(g_zr + ((size_t)src << 6) + (lane << 1)));
            ax += v.x; ay += v.y;
        }
    }
    float2 o; o.x = fmaxf(ax, 0.f); o.y = fmaxf(ay, 0.f);
    *(float2*)(g_xpf + ((size_t)n << 6) + (lane << 1)) = o;
}

// ---------------- readout MLP ----------------
__global__ void k_readout(const float* __restrict__ W0, const float* __restrict__ b0,
                          const float* __restrict__ W1, const float* __restrict__ b1,
                          const float* __restrict__ W2, const float* __restrict__ b2,
                          const float* __restrict__ lW, const float* __restrict__ lb,
                          float* __restrict__ out) {
    __shared__ float m[128];
    __shared__ float h0[64];
    __shared__ float h1[32];
    __shared__ float h2s[16];
    int b = blockIdx.x, t = threadIdx.x;  // 64 threads
    m[t] = g_x1[b * 64 + t];
    m[64 + t] = g_x2[b * 64 + t];
    __syncthreads();
    float acc = __ldg(&b0[t]);
    #pragma unroll 4
    for (int k = 0; k < 128; k++) acc = fmaf(m[k], __ldg(&W0[k * 64 + t]), acc);
    h0[t] = fmaxf(acc, 0.f);
    __syncthreads();
    if (t < 32) {
        float a = __ldg(&b1[t]);
        for (int k = 0; k < 64; k++) a = fmaf(h0[k], __ldg(&W1[k * 32 + t]), a);
        h1[t] = fmaxf(a, 0.f);
    }
    __syncthreads();
    if (t < 16) {
        float a = __ldg(&b2[t]);
        for (int k = 0; k < 32; k++) a = fmaf(h1[k], __ldg(&W2[k * 16 + t]), a);
        h2s[t] = fmaxf(a, 0.f);
    }
    __syncthreads();
    if (t == 0) {
        float a = __ldg(&lb[0]);
        for (int k = 0; k < 16; k++) a = fmaf(h2s[k], __ldg(&lW[k]), a);
        out[b] = a;
    }
}

// ---------------- launch ----------------
extern "C" void kernel_launch(void* const* d_in, const int* in_sizes, int n_in,
                              void* d_out, int out_size) {
    (void)in_sizes; (void)n_in; (void)out_size;
    const float* x    = (const float*)d_in[0];
    const int*   ei   = (const int*)d_in[1];
    const int*   ea   = (const int*)d_in[2];
    const float* isoT = (const float*)d_in[4];
    const int*   ei2  = (const int*)d_in[5];
    const int*   asg  = (const int*)d_in[6];
    const float* embW = (const float*)d_in[8];
    const float* embB = (const float*)d_in[9];
    const float* gW1  = (const float*)d_in[10];
    const float* gb1  = (const float*)d_in[11];
    const float* gW2  = (const float*)d_in[12];
    const float* gb2  = (const float*)d_in[13];
    const float* ee1  = (const float*)d_in[14];
    const float* ee2  = (const float*)d_in[15];
    const float* bng  = (const float*)d_in[16];
    const float* bnb  = (const float*)d_in[17];
    const float* i1rW = (const float*)d_in[18];
    const float* i1rb = (const float*)d_in[19];
    const float* i1oW = (const float*)d_in[20];
    const float* i2rW = (const float*)d_in[21];
    const float* i2rb = (const float*)d_in[22];
    const float* i2oW = (const float*)d_in[23];
    const float* rW0  = (const float*)d_in[24];
    const float* rb0  = (const float*)d_in[25];
    const float* rW1  = (const float*)d_in[26];
    const float* rb1  = (const float*)d_in[27];
    const float* rW2  = (const float*)d_in[28];
    const float* rb2  = (const float*)d_in[29];
    const float* lW   = (const float*)d_in[30];
    const float* lb   = (const float*)d_in[31];
    float* out = (float*)d_out;

    // ---- CSR build: count -> reserve (atomic, unordered bases) -> fill ----
    k_zero<<<256, 256>>>();
    k_count1<<<NE / 256, 256>>>(ei, ea);
    k_count2<<<NE2 / 256, 256>>>(ei2);
    k_reserve<<<(NN + NN2) / 256, 256>>>();
    k_fill1<<<NE / 256, 256>>>(ei);
    k_fill2<<<NE2 / 256, 256>>>(ei2);

    // ---- node embedding ----
    k_embed<<<2048, 128>>>(x, embW, embB);

    // ---- GIN stack ----
    for (int l = 0; l < NL; l++) {
        k_agg1<<<NN / 8, 256>>>(ee1 + (size_t)l * 6 * ND, ee2 + (size_t)l * 3 * ND);
        k_mlp<<<1184, 128>>>(gW1 + (size_t)l * ND * 128, gb1 + (size_t)l * 128,
                             gW2 + (size_t)l * 128 * ND, gb2 + (size_t)l * ND);
        k_norm<<<NN * 16 / 256, 256>>>(bng + (size_t)l * ND, bnb + (size_t)l * ND,
                                       (l < NL - 1) ? 1 : 0);
    }

    // ---- graph mean pool of node_rep ----
    k_pool<<<NG, 64>>>(0);

    // ---- 2-set branch ----
    k_iso<<<(NN2 + 255) / 256, 256>>>(isoT);
    k_xp<<<NN2 * ND / 256, 256>>>(asg);
    k_proj<<<1184, 128>>>(i1rW, i1oW, 1);
    k_cagg<<<NN2 / 8, 256>>>(i1rb);
    k_proj<<<1184, 128>>>(i2rW, i2oW, 0);
    k_cagg<<<NN2 / 8, 256>>>(i2rb);
    k_pool<<<NG, 64>>>(1);

    // ---- readout ----
    k_readout<<<NG, 64>>>(rW0, rb0, rW1, rb1, rW2, rb2, lW, lb, out);
}

// round 4
// speedup vs baseline: 1.3816x; 1.2220x over previous
#include <cuda_runtime.h>
#include <cstdint>

#define NN   51200
#define NE   819200
#define NG   256
#define NN2  102400
#define NA   204800
#define NE2  409600
#define ND   64
#define NL   5
#define NNI2 36
#define NNAF 40
#define FEPS 1e-5f

typedef unsigned long long u64;

// ---------------- f32x2 packed helpers ----------------
__device__ __forceinline__ u64 pk2(float x, float y) {
    u64 r; asm("mov.b64 %0, {%1,%2};" : "=l"(r) : "f"(x), "f"(y)); return r;
}
__device__ __forceinline__ float2 up2(u64 v) {
    float2 r; asm("mov.b64 {%0,%1}, %2;" : "=f"(r.x), "=f"(r.y) : "l"(v)); return r;
}
__device__ __forceinline__ u64 f2fma(float a, u64 b, u64 c) {
    u64 d;
    asm("{\n\t.reg .b64 ra;\n\tmov.b64 ra, {%1,%1};\n\tfma.rn.f32x2 %0, ra, %2, %3;\n\t}"
        : "=l"(d) : "f"(a), "l"(b), "l"(c));
    return d;
}
__device__ __forceinline__ u64 add2(u64 a, u64 b) {
    u64 d; asm("add.rn.f32x2 %0, %1, %2;" : "=l"(d) : "l"(a), "l"(b)); return d;
}

// ---------------- device scratch ----------------
__device__ float g_h[NN * ND];
__device__ float g_agg[NN * ND];
__device__ float g_h2[NN * ND];

__device__ int g_cnt12[NN * 12];
__device__ int g_deg1[NN];
__device__ int g_base1[NN];
__device__ int g_cursor1[NN];
__device__ int g_adj1[NE];
__device__ int g_total1;

__device__ int g_deg2[NN2];
__device__ int g_base2[NN2];
__device__ int g_cursor2[NN2];
__device__ int g_adj2[NE2];
__device__ int g_total2;

__device__ float g_xpf[NN2 * ND];
__device__ int   g_iso[NN2];
__device__ float g_zr[NN2 * ND];
__device__ float g_zroot[NN2 * ND];

__device__ float g_bnsum[ND];
__device__ float g_bnsq[ND];

__device__ float g_x1[NG * ND];
__device__ float g_x2[NG * ND];

// ---------------- zero ----------------
__global__ void k_zero() {
    int i = blockIdx.x * blockDim.x + threadIdx.x;
    int stride = gridDim.x * blockDim.x;
    for (int j = i; j < NN * 12; j += stride) g_cnt12[j] = 0;
    for (int j = i; j < NN2; j += stride) g_deg2[j] = 0;
    if (i == 0) { g_total1 = 0; g_total2 = 0; }
}

// ---------------- counts (merged) ----------------
__global__ void k_count(const int* __restrict__ ei, const int* __restrict__ ea,
                        const int* __restrict__ ei2) {
    int e = blockIdx.x * blockDim.x + threadIdx.x;
    if (e < NE) {
        int dst = ei[NE + e];
        atomicAdd(&g_cnt12[dst * 12 + ea[2 * e] * 3 + ea[2 * e + 1]], 1);
    } else if (e < NE + NE2) {
        int e2 = e - NE;
        atomicAdd(&g_deg2[ei2[NE2 + e2]], 1);
    }
}

// ---------------- reserve CSR ranges (warp-aggregated atomics) ----------------
__global__ void k_reserve() {
    int i = blockIdx.x * blockDim.x + threadIdx.x;
    int lane = threadIdx.x & 31;
    if (i < NN) {
        int d = 0;
        #pragma unroll
        for (int c = 0; c < 12; c++) d += g_cnt12[i * 12 + c];
        g_deg1[i] = d;
        int incl = d;
        #pragma unroll
        for (int o = 1; o < 32; o <<= 1) {
            int t = __shfl_up_sync(0xffffffffu, incl, o);
            if (lane >= o) incl += t;
        }
        int tot = __shfl_sync(0xffffffffu, incl, 31);
        int base = 0;
        if (lane == 0) base = atomicAdd(&g_total1, tot);
        base = __shfl_sync(0xffffffffu, base, 0);
        int start = base + incl - d;
        g_base1[i] = start; g_cursor1[i] = start;
    } else if (i < NN + NN2) {
        int j = i - NN;
        int d = g_deg2[j];
        int incl = d;
        #pragma unroll
        for (int o = 1; o < 32; o <<= 1) {
            int t = __shfl_up_sync(0xffffffffu, incl, o);
            if (lane >= o) incl += t;
        }
        int tot = __shfl_sync(0xffffffffu, incl, 31);
        int base = 0;
        if (lane == 0) base = atomicAdd(&g_total2, tot);
        base = __shfl_sync(0xffffffffu, base, 0);
        int start = base + incl - d;
        g_base2[j] = start; g_cursor2[j] = start;
    }
}

// ---------------- CSR fill (merged) ----------------
__global__ void k_fill(const int* __restrict__ ei, const int* __restrict__ ei2) {
    int e = blockIdx.x * blockDim.x + threadIdx.x;
    if (e < NE) {
        int dst = ei[NE + e];
        int pos = atomicAdd(&g_cursor1[dst], 1);
        g_adj1[pos] = ei[e];
    } else if (e < NE + NE2) {
        int e2 = e - NE;
        int dst = ei2[NE2 + e2];
        int pos = atomicAdd(&g_cursor2[dst], 1);
        g_adj2[pos] = ei2[e2];
    }
}

// ---------------- embed: h = relu(x @ embW + embB) ----------------
__global__ __launch_bounds__(128) void k_embed(const float* __restrict__ x,
                                               const float* __restrict__ W,
                                               const float* __restrict__ b) {
    __shared__ float Ws[NNAF * ND];
    __shared__ float bs[ND];
    __shared__ float row[2][NNAF];
    int tid = threadIdx.x;
    for (int i = tid; i < NNAF * ND; i += 128) Ws[i] = W[i];
    if (tid < 64) bs[tid] = b[tid];
    __syncthreads();
    int slot = tid >> 6, c = tid & 63;
    for (int base = blockIdx.x * 2; base < NN; base += gridDim.x * 2) {
        if (tid < 2 * NNAF) row[tid / NNAF][tid % NNAF] = x[(size_t)base * NNAF + tid];
        __syncthreads();
        float acc = bs[c];
        #pragma unroll
        for (int k = 0; k < NNAF; k++) acc = fmaf(row[slot][k], Ws[k * 64 + c], acc);
        g_h[(size_t)(base + slot) * 64 + c] = fmaxf(acc, 0.f);
        __syncthreads();
    }
}

// ---------------- GIN aggregation (warp per node) + bn-stat zero ----------------
__global__ __launch_bounds__(256) void k_agg1(const float* __restrict__ e1,
                                              const float* __restrict__ e2) {
    __shared__ float comb[12][64];
    __shared__ float selfe[64];
    int tid = threadIdx.x;
    for (int idx = tid; idx < 12 * 64; idx += 256) {
        int cc = idx >> 6, d = idx & 63;
        comb[cc][d] = e1[(cc / 3) * 64 + d] + e2[(cc % 3) * 64 + d];
    }
    if (tid < 64) selfe[tid] = e1[4 * 64 + tid] + e2[0 * 64 + tid];
    if (blockIdx.x == 0 && tid < 64) { g_bnsum[tid] = 0.f; g_bnsq[tid] = 0.f; }
    __syncthreads();

    int warp = (blockIdx.x * 256 + tid) >> 5;
    if (warp >= NN) return;
    int n = warp;
    int lane = tid & 31;

    int cnt = (lane < 12) ? __ldg(&g_cnt12[n * 12 + lane]) : 0;

    float2 hv = __ldg((const float2*)(g_h + ((size_t)n << 6) + (lane << 1)));
    float2 se = ((const float2*)selfe)[lane];
    float ax0 = hv.x + se.x, ay0 = hv.y + se.y;
    float ax1 = 0.f, ay1 = 0.f;

    #pragma unroll
    for (int c = 0; c < 12; c++) {
        float cc = (float)__shfl_sync(0xffffffffu, cnt, c);
        float2 w = ((const float2*)comb[c])[lane];
        if (c & 1) { ax1 = fmaf(cc, w.x, ax1); ay1 = fmaf(cc, w.y, ay1); }
        else       { ax0 = fmaf(cc, w.x, ax0); ay0 = fmaf(cc, w.y, ay0); }
    }

    int beg = __ldg(&g_base1[n]);
    int end = beg + __ldg(&g_deg1[n]);
    int j = beg;
    for (; j + 32 <= end; j += 32) {
        int s = __ldg(&g_adj1[j + lane]);
        #pragma unroll
        for (int t = 0; t < 32; t++) {
            int src = __shfl_sync(0xffffffffu, s, t);
            float2 v = __ldg((const float2*)(g_h + ((size_t)src << 6) + (lane << 1)));
            if (t & 1) { ax1 += v.x; ay1 += v.y; }
            else       { ax0 += v.x; ay0 += v.y; }
        }
    }
    if (j < end) {
        int idx = j + lane;
        int s = (idx < end) ? __ldg(&g_adj1[idx]) : 0;
        int c = end - j;
        for (int t = 0; t < c; t++) {
            int src = __shfl_sync(0xffffffffu, s, t);
            float2 v = __ldg((const float2*)(g_h + ((size_t)src << 6) + (lane << 1)));
            if (t & 1) { ax1 += v.x; ay1 += v.y; }
            else       { ax0 += v.x; ay0 += v.y; }
        }
    }
    float2 o; o.x = ax0 + ax1; o.y = ay0 + ay1;
    *(float2*)(g_agg + ((size_t)n << 6) + (lane << 1)) = o;
}

// ---------------- GIN MLP v3: 4-row batch, K-split, ILP-4 ----------------
__global__ __launch_bounds__(256) void k_mlp(const float* __restrict__ W1,
                                             const float* __restrict__ b1,
                                             const float* __restrict__ W2,
                                             const float* __restrict__ b2) {
    __shared__ __align__(16) float rowf[4][64];
    __shared__ __align__(16) float midf[4][128];
    __shared__ u64 part[1024];
    int tid = threadIdx.x;
    int p1 = tid & 63, q1 = tid >> 6;   // stage1: col-pair p1 of 64, K-quarter q1 of 4
    int p2 = tid & 31, q2 = tid >> 5;   // stage2: col-pair p2 of 32, K-eighth q2 of 8

    u64 w1p[16], w2p[16];
    #pragma unroll
    for (int kk = 0; kk < 16; kk++) {
        int k = q1 * 16 + kk;
        w1p[kk] = pk2(__ldg(&W1[k * 128 + 2 * p1]), __ldg(&W1[k * 128 + 2 * p1 + 1]));
    }
    #pragma unroll
    for (int kk = 0; kk < 16; kk++) {
        int k = q2 * 16 + kk;
        w2p[kk] = pk2(__ldg(&W2[k * 64 + 2 * p2]), __ldg(&W2[k * 64 + 2 * p2 + 1]));
    }
    u64 bias1 = pk2(__ldg(&b1[2 * p1]), __ldg(&b1[2 * p1 + 1]));
    u64 bias2 = pk2(__ldg(&b2[2 * p2]), __ldg(&b2[2 * p2 + 1]));

    float2 lsum = make_float2(0.f, 0.f), lsq = make_float2(0.f, 0.f);

    for (int rq = blockIdx.x; rq < NN / 4; rq += gridDim.x) {
        int base = rq * 4;
        ((float*)rowf)[tid] = g_agg[(size_t)base * 64 + tid];
        __syncthreads();
        // stage 1: four independent row accumulators
        u64 a0 = 0ull, a1 = 0ull, a2 = 0ull, a3 = 0ull;
        #pragma unroll
        for (int kk = 0; kk < 16; kk++) {
            int k = q1 * 16 + kk;
            float r0 = rowf[0][k], r1 = rowf[1][k], r2 = rowf[2][k], r3 = rowf[3][k];
            a0 = f2fma(r0, w1p[kk], a0);
            a1 = f2fma(r1, w1p[kk], a1);
            a2 = f2fma(r2, w1p[kk], a2);
            a3 = f2fma(r3, w1p[kk], a3);
        }
        part[q1 * 256 + 0 * 64 + p1] = a0;
        part[q1 * 256 + 1 * 64 + p1] = a1;
        part[q1 * 256 + 2 * 64 + p1] = a2;
        part[q1 * 256 + 3 * 64 + p1] = a3;
        __syncthreads();
        {
            int rr = tid >> 6, pp = tid & 63;
            u64 s = add2(add2(part[0 * 256 + rr * 64 + pp], part[1 * 256 + rr * 64 + pp]),
                         add2(part[2 * 256 + rr * 64 + pp], part[3 * 256 + rr * 64 + pp]));
            float2 v = up2(add2(s, bias1));
            midf[rr][2 * pp]     = fmaxf(v.x, 0.f);
            midf[rr][2 * pp + 1] = fmaxf(v.y, 0.f);
        }
        __syncthreads();
        // stage 2
        u64 c0 = 0ull, c1 = 0ull, c2 = 0ull, c3 = 0ull;
        #pragma unroll
        for (int kk = 0; kk < 16; kk++) {
            int k = q2 * 16 + kk;
            float m0 = midf[0][k], m1 = midf[1][k], m2 = midf[2][k], m3 = midf[3][k];
            c0 = f2fma(m0, w2p[kk], c0);
            c1 = f2fma(m1, w2p[kk], c1);
            c2 = f2fma(m2, w2p[kk], c2);
            c3 = f2fma(m3, w2p[kk], c3);
        }
        part[q2 * 128 + 0 * 32 + p2] = c0;
        part[q2 * 128 + 1 * 32 + p2] = c1;
        part[q2 * 128 + 2 * 32 + p2] = c2;
        part[q2 * 128 + 3 * 32 + p2] = c3;
        __syncthreads();
        if (tid < 128) {
            int rr = tid >> 5, pp = tid & 31;
            u64 s01 = add2(part[0 * 128 + rr * 32 + pp], part[1 * 128 + rr * 32 + pp]);
            u64 s23 = add2(part[2 * 128 + rr * 32 + pp], part[3 * 128 + rr * 32 + pp]);
            u64 s45 = add2(part[4 * 128 + rr * 32 + pp], part[5 * 128 + rr * 32 + pp]);
            u64 s67 = add2(part[6 * 128 + rr * 32 + pp], part[7 * 128 + rr * 32 + pp]);
            u64 s = add2(add2(s01, s23), add2(s45, s67));
            float2 v = up2(add2(s, bias2));
            *(float2*)(g_h2 + (size_t)(base + rr) * 64 + 2 * pp) = v;
            lsum.x += v.x; lsum.y += v.y;
            lsq.x += v.x * v.x; lsq.y += v.y * v.y;
        }
        __syncthreads();
    }
    if (tid < 128) {
        int pp = tid & 31;
        atomicAdd(&g_bnsum[2 * pp], lsum.x);
        atomicAdd(&g_bnsum[2 * pp + 1], lsum.y);
        atomicAdd(&g_bnsq[2 * pp], lsq.x);
        atomicAdd(&g_bnsq[2 * pp + 1], lsq.y);
    }
}

// ---------------- BN normalize (+relu) ----------------
__global__ void k_norm(const float* __restrict__ gamma, const float* __restrict__ beta,
                       int relu) {
    __shared__ float sc[64], sh[64];
    int tid = threadIdx.x;
    if (tid < 64) {
        float mu = g_bnsum[tid] * (1.f / (float)NN);
        float var = g_bnsq[tid] * (1.f / (float)NN) - mu * mu;
        float s = gamma[tid] * rsqrtf(var + FEPS);
        sc[tid] = s;
        sh[tid] = beta[tid] - mu * s;
    }
    __syncthreads();
    int idx = blockIdx.x * blockDim.x + tid;
    if (idx >= NN * 16) return;
    float4 v = *(const float4*)(g_h2 + (size_t)idx * 4);
    int c = (idx & 15) * 4;
    float4 o;
    o.x = sc[c + 0] * v.x + sh[c + 0];
    o.y = sc[c + 1] * v.y + sh[c + 1];
    o.z = sc[c + 2] * v.z + sh[c + 2];
    o.w = sc[c + 3] * v.w + sh[c + 3];
    if (relu) {
        o.x = fmaxf(o.x, 0.f); o.y = fmaxf(o.y, 0.f);
        o.z = fmaxf(o.z, 0.f); o.w = fmaxf(o.w, 0.f);
    }
    *(float4*)(g_h + (size_t)idx * 4) = o;
}

// ---------------- pools ----------------
__global__ void k_pool(int which) {
    int b = blockIdx.x, t = threadIdx.x;
    if (which == 0) {
        const float* p = g_h + (size_t)b * 200 * 64 + t;
        float s = 0.f;
        for (int r = 0; r < 200; r++) s += p[(size_t)r * 64];
        g_x1[b * 64 + t] = s * (1.f / 200.f);
    } else {
        const float* p = g_xpf + (size_t)b * 400 * 64 + t;
        float s = 0.f;
        for (int r = 0; r < 400; r++) s += p[(size_t)r * 64];
        g_x2[b * 64 + t] = s * (1.f / 400.f);
    }
}

// ---------------- 2-set branch ----------------
__global__ void k_iso(const float* __restrict__ isoT) {
    int i = blockIdx.x * blockDim.x + threadIdx.x;
    if (i >= NN2) return;
    const float4* row = (const float4*)(isoT + (size_t)i * NNI2);
    int r = 0;
    #pragma unroll
    for (int q = 0; q < 9; q++) {
        float4 v = __ldg(&row[q]);
        if (v.x > 0.5f) r = 4 * q;
        if (v.y > 0.5f) r = 4 * q + 1;
        if (v.z > 0.5f) r = 4 * q + 2;
        if (v.w > 0.5f) r = 4 * q + 3;
    }
    g_iso[i] = r;
}

// project v3: 4-row batch; mode1 fuses the assignment-pool gather + iso lookup
__global__ __launch_bounds__(256) void k_proj(const float* __restrict__ Wrel,
                                              const float* __restrict__ Wroot,
                                              const int* __restrict__ asg,
                                              int mode) {
    __shared__ __align__(16) float rowf[4][64];
    __shared__ u64 part[1024];
    __shared__ float isoWs[2 * NNI2 * 64];
    __shared__ int si[4];
    int tid = threadIdx.x;
    int m = tid >> 7;           // 0 rel, 1 root
    int rest = tid & 127;
    int p = rest & 31;          // col pair of 32
    int q = rest >> 5;          // K-quarter of 4
    const float* Wm = m ? Wroot : Wrel;

    u64 wp[16];
    #pragma unroll
    for (int kk = 0; kk < 16; kk++) {
        int k = q * 16 + kk;
        wp[kk] = pk2(__ldg(&Wm[k * 64 + 2 * p]), __ldg(&Wm[k * 64 + 2 * p + 1]));
    }
    if (mode) {
        for (int idx = tid; idx < 2 * NNI2 * 64; idx += 256) {
            int mm = idx / (NNI2 * 64);
            int rest2 = idx - mm * (NNI2 * 64);
            const float* Wx = mm ? Wroot : Wrel;
            isoWs[idx] = __ldg(&Wx[(64 + rest2 / 64) * 64 + (rest2 & 63)]);
        }
    }
    __syncthreads();

    for (int rq = blockIdx.x; rq < NN2 / 4; rq += gridDim.x) {
        int base = rq * 4;
        {
            int rr = tid >> 6, c = tid & 63;
            int i = base + rr;
            if (mode) {
                int a = __ldg(&asg[2 * i]);
                int b = __ldg(&asg[2 * i + 1]);
                rowf[rr][c] = 0.5f * (__ldg(&g_h[(size_t)a * 64 + c]) +
                                      __ldg(&g_h[(size_t)b * 64 + c]));
                if (tid < 4) si[tid] = __ldg(&g_iso[base + tid]);
            } else {
                rowf[rr][c] = g_xpf[(size_t)i * 64 + c];
            }
        }
        __syncthreads();
        u64 a0 = 0ull, a1 = 0ull, a2 = 0ull, a3 = 0ull;
        #pragma unroll
        for (int kk = 0; kk < 16; kk++) {
            int k = q * 16 + kk;
            float r0 = rowf[0][k], r1 = rowf[1][k], r2 = rowf[2][k], r3 = rowf[3][k];
            a0 = f2fma(r0, wp[kk], a0);
            a1 = f2fma(r1, wp[kk], a1);
            a2 = f2fma(r2, wp[kk], a2);
            a3 = f2fma(r3, wp[kk], a3);
        }
        part[m * 512 + q * 128 + 0 * 32 + p] = a0;
        part[m * 512 + q * 128 + 1 * 32 + p] = a1;
        part[m * 512 + q * 128 + 2 * 32 + p] = a2;
        part[m * 512 + q * 128 + 3 * 32 + p] = a3;
        __syncthreads();
        {
            int mm = tid >> 7, rr = (tid >> 5) & 3, pp = tid & 31;
            u64 s = add2(add2(part[mm * 512 + 0 * 128 + rr * 32 + pp],
                              part[mm * 512 + 1 * 128 + rr * 32 + pp]),
                         add2(part[mm * 512 + 2 * 128 + rr * 32 + pp],
                              part[mm * 512 + 3 * 128 + rr * 32 + pp]));
            float2 v = up2(s);
            if (mode) {
                int is = si[rr];
                v.x += isoWs[mm * (NNI2 * 64) + is * 64 + 2 * pp];
                v.y += isoWs[mm * (NNI2 * 64) + is * 64 + 2 * pp + 1];
            }
            float* outp = mm ? g_zroot : g_zr;
            *(float2*)(outp + (size_t)(base + rr) * 64 + 2 * pp) = v;
        }
        __syncthreads();
    }
}

// conv aggregate: xpf[i] = relu( sum_{src} zr[src] + brel + zroot[i] )
__global__ __launch_bounds__(256) void k_cagg(const float* __restrict__ brel) {
    int warp = (blockIdx.x * blockDim.x + threadIdx.x) >> 5;
    int lane = threadIdx.x & 31;
    if (warp >= NN2) return;
    int n = warp;
    float2 z = __ldg((const float2*)(g_zroot + ((size_t)n << 6) + (lane << 1)));
    float ax0 = z.x + __ldg(&brel[2 * lane]);
    float ay0 = z.y + __ldg(&brel[2 * lane + 1]);
    float ax1 = 0.f, ay1 = 0.f;
    int beg = __ldg(&g_base2[n]);
    int end = beg + __ldg(&g_deg2[n]);
    int j = beg;
    for (; j + 32 <= end; j += 32) {
        int s = __ldg(&g_adj2[j + lane]);
        #pragma unroll
        for (int t = 0; t < 32; t++) {
            int src = __shfl_sync(0xffffffffu, s, t);
            float2 v = __ldg((const float2*)(g_zr + ((size_t)src << 6) + (lane << 1)));
            if (t & 1) { ax1 += v.x; ay1 += v.y; }
            else       { ax0 += v.x; ay0 += v.y; }
        }
    }
    if (j < end) {
        int idx = j + lane;
        int s = (idx < end) ? __ldg(&g_adj2[idx]) : 0;
        int c = end - j;
        for (int t = 0; t < c; t++) {
            int src = __shfl_sync(0xffffffffu, s, t);
            float2 v = __ldg((const float2*)(g_zr + ((size_t)src << 6) + (lane << 1)));
            if (t & 1) { ax1 += v.x; ay1 += v.y; }
            else       { ax0 += v.x; ay0 += v.y; }
        }
    }
    float2 o; o.x = fmaxf(ax0 + ax1, 0.f); o.y = fmaxf(ay0 + ay1, 0.f);
    *(float2*)(g_xpf + ((size_t)n << 6) + (lane << 1)) = o;
}

// ---------------- readout MLP ----------------
__global__ void k_readout(const float* __restrict__ W0, const float* __restrict__ b0,
                          const float* __restrict__ W1, const float* __restrict__ b1,
                          const float* __restrict__ W2, const float* __restrict__ b2,
                          const float* __restrict__ lW, const float* __restrict__ lb,
                          float* __restrict__ out) {
    __shared__ float m[128];
    __shared__ float h0[64];
    __shared__ float h1[32];
    __shared__ float h2s[16];
    int b = blockIdx.x, t = threadIdx.x;
    m[t] = g_x1[b * 64 + t];
    m[64 + t] = g_x2[b * 64 + t];
    __syncthreads();
    float acc = __ldg(&b0[t]);
    #pragma unroll 4
    for (int k = 0; k < 128; k++) acc = fmaf(m[k], __ldg(&W0[k * 64 + t]), acc);
    h0[t] = fmaxf(acc, 0.f);
    __syncthreads();
    if (t < 32) {
        float a = __ldg(&b1[t]);
        for (int k = 0; k < 64; k++) a = fmaf(h0[k], __ldg(&W1[k * 32 + t]), a);
        h1[t] = fmaxf(a, 0.f);
    }
    __syncthreads();
    if (t < 16) {
        float a = __ldg(&b2[t]);
        for (int k = 0; k < 32; k++) a = fmaf(h1[k], __ldg(&W2[k * 16 + t]), a);
        h2s[t] = fmaxf(a, 0.f);
    }
    __syncthreads();
    if (t == 0) {
        float a = __ldg(&lb[0]);
        for (int k = 0; k < 16; k++) a = fmaf(h2s[k], __ldg(&lW[k]), a);
        out[b] = a;
    }
}

// ---------------- launch ----------------
extern "C" void kernel_launch(void* const* d_in, const int* in_sizes, int n_in,
                              void* d_out, int out_size) {
    (void)in_sizes; (void)n_in; (void)out_size;
    const float* x    = (const float*)d_in[0];
    const int*   ei   = (const int*)d_in[1];
    const int*   ea   = (const int*)d_in[2];
    const float* isoT = (const float*)d_in[4];
    const int*   ei2  = (const int*)d_in[5];
    const int*   asg  = (const int*)d_in[6];
    const float* embW = (const float*)d_in[8];
    const float* embB = (const float*)d_in[9];
    const float* gW1  = (const float*)d_in[10];
    const float* gb1  = (const float*)d_in[11];
    const float* gW2  = (const float*)d_in[12];
    const float* gb2  = (const float*)d_in[13];
    const float* ee1  = (const float*)d_in[14];
    const float* ee2  = (const float*)d_in[15];
    const float* bng  = (const float*)d_in[16];
    const float* bnb  = (const float*)d_in[17];
    const float* i1rW = (const float*)d_in[18];
    const float* i1rb = (const float*)d_in[19];
    const float* i1oW = (const float*)d_in[20];
    const float* i2rW = (const float*)d_in[21];
    const float* i2rb = (const float*)d_in[22];
    const float* i2oW = (const float*)d_in[23];
    const float* rW0  = (const float*)d_in[24];
    const float* rb0  = (const float*)d_in[25];
    const float* rW1  = (const float*)d_in[26];
    const float* rb1  = (const float*)d_in[27];
    const float* rW2  = (const float*)d_in[28];
    const float* rb2  = (const float*)d_in[29];
    const float* lW   = (const float*)d_in[30];
    const float* lb   = (const float*)d_in[31];
    float* out = (float*)d_out;

    // ---- CSR build ----
    k_zero<<<256, 256>>>();
    k_count<<<(NE + NE2) / 256, 256>>>(ei, ea, ei2);
    k_reserve<<<(NN + NN2) / 256, 256>>>();
    k_fill<<<(NE + NE2) / 256, 256>>>(ei, ei2);

    // ---- node embedding ----
    k_embed<<<2048, 128>>>(x, embW, embB);

    // ---- GIN stack ----
    for (int l = 0; l < NL; l++) {
        k_agg1<<<NN / 8, 256>>>(ee1 + (size_t)l * 6 * ND, ee2 + (size_t)l * 3 * ND);
        k_mlp<<<1280, 256>>>(gW1 + (size_t)l * ND * 128, gb1 + (size_t)l * 128,
                             gW2 + (size_t)l * 128 * ND, gb2 + (size_t)l * ND);
        k_norm<<<NN * 16 / 256, 256>>>(bng + (size_t)l * ND, bnb + (size_t)l * ND,
                                       (l < NL - 1) ? 1 : 0);
    }

    // ---- graph mean pool of node_rep ----
    k_pool<<<NG, 64>>>(0);

    // ---- 2-set branch ----
    k_iso<<<(NN2 + 255) / 256, 256>>>(isoT);
    k_proj<<<1184, 256>>>(i1rW, i1oW, asg, 1);
    k_cagg<<<NN2 / 8, 256>>>(i1rb);
    k_proj<<<1184, 256>>>(i2rW, i2oW, asg, 0);
    k_cagg<<<NN2 / 8, 256>>>(i2rb);
    k_pool<<<NG, 64>>>(1);

    // ---- readout ----
    k_readout<<<NG, 64>>>(rW0, rb0, rW1, rb1, rW2, rb2, lW, lb, out);
}